// round 1
// baseline (speedup 1.0000x reference)
#include <cuda_runtime.h>
#include <math.h>

#define B_    2
#define S_    2048
#define HID_  1024
#define NH_   16
#define HD_   64
#define MTOT  (B_ * S_)

// Scratch (static device allocation — no cudaMalloc allowed)
__device__ float g_Q[MTOT * HID_];
__device__ float g_K[MTOT * HID_];
__device__ float g_V[MTOT * HID_];
__device__ float g_C[MTOT * HID_];

// ============================================================
// SGEMM: C[M,N] = A[M,K] @ W[N,K]^T + bias   (torch Linear)
// 128x128 tile, BK=8, 256 threads, 8x8 per thread
// ============================================================
#define BM 128
#define BN 128
#define BK 8

__global__ __launch_bounds__(256) void sgemm_bias(
    const float* __restrict__ A, const float* __restrict__ W,
    const float* __restrict__ bias, float* __restrict__ C,
    int M, int N, int K)
{
    __shared__ float As[BK][BM];
    __shared__ float Bs[BK][BN];

    const int bm = blockIdx.y * BM;
    const int bn = blockIdx.x * BN;
    const int t  = threadIdx.x;
    const int tx = t & 15;
    const int ty = t >> 4;

    const int lrow = t >> 1;          // 0..127
    const int lk   = (t & 1) * 4;     // 0 or 4

    const float* Ap = A + (size_t)(bm + lrow) * K + lk;
    const float* Wp = W + (size_t)(bn + lrow) * K + lk;

    float acc[8][8];
#pragma unroll
    for (int i = 0; i < 8; i++)
#pragma unroll
        for (int j = 0; j < 8; j++) acc[i][j] = 0.0f;

    for (int k0 = 0; k0 < K; k0 += BK) {
        float4 a = *(const float4*)(Ap + k0);
        float4 w = *(const float4*)(Wp + k0);
        As[lk + 0][lrow] = a.x; As[lk + 1][lrow] = a.y;
        As[lk + 2][lrow] = a.z; As[lk + 3][lrow] = a.w;
        Bs[lk + 0][lrow] = w.x; Bs[lk + 1][lrow] = w.y;
        Bs[lk + 2][lrow] = w.z; Bs[lk + 3][lrow] = w.w;
        __syncthreads();

#pragma unroll
        for (int k = 0; k < BK; k++) {
            float4 a0 = *(const float4*)&As[k][ty * 4];
            float4 a1 = *(const float4*)&As[k][64 + ty * 4];
            float4 b0 = *(const float4*)&Bs[k][tx * 4];
            float4 b1 = *(const float4*)&Bs[k][64 + tx * 4];
            float ra[8] = {a0.x, a0.y, a0.z, a0.w, a1.x, a1.y, a1.z, a1.w};
            float rb[8] = {b0.x, b0.y, b0.z, b0.w, b1.x, b1.y, b1.z, b1.w};
#pragma unroll
            for (int i = 0; i < 8; i++)
#pragma unroll
                for (int j = 0; j < 8; j++)
                    acc[i][j] += ra[i] * rb[j];
        }
        __syncthreads();
    }

#pragma unroll
    for (int i = 0; i < 8; i++) {
        int r = bm + ((i < 4) ? (ty * 4 + i) : (64 + ty * 4 + (i - 4)));
#pragma unroll
        for (int jj = 0; jj < 2; jj++) {
            int c = bn + jj * 64 + tx * 4;
            float4 v;
            v.x = acc[i][jj * 4 + 0] + bias[c + 0];
            v.y = acc[i][jj * 4 + 1] + bias[c + 1];
            v.z = acc[i][jj * 4 + 2] + bias[c + 2];
            v.w = acc[i][jj * 4 + 3] + bias[c + 3];
            *(float4*)&C[(size_t)r * N + c] = v;
        }
    }
}

// ============================================================
// Flash-style ConsMax attention.
//   scores = (Q K^T)/8 + (1-mask)*(-1e4)
//   probs  = exp(scores - rowmax(scores)) / gamma   (beta cancels)
//   ctx    = probs @ V     (NO sum normalization)
// Br=64 queries/block, Bc=32 keys/tile, 256 threads (16x16).
// Q/K/V layout: [M, HID] row-major; head h occupies cols h*64..h*64+63.
// ============================================================
#define BR 64
#define BC 32

__global__ __launch_bounds__(256) void consmax_attn(
    const float* __restrict__ Q, const float* __restrict__ K,
    const float* __restrict__ V, const float* __restrict__ mask,
    const float* __restrict__ gamma, float* __restrict__ Ctx)
{
    __shared__ float Qs[BR][HD_];         // 16 KB
    __shared__ float KsT[HD_][BC + 1];    // transposed K tile, 8.25 KB
    __shared__ float Vs[BC][HD_];         // 8 KB
    __shared__ float Ps[BR][BC];          // 8 KB

    const int qb = blockIdx.x;   // query block
    const int h  = blockIdx.y;   // head
    const int b  = blockIdx.z;   // batch
    const int t  = threadIdx.x;
    const int tx = t & 15;
    const int ty = t >> 4;

    const size_t rowbase = (size_t)(b * S_ + qb * BR);

    // Load Q tile, pre-scaled by 1/sqrt(HD)=0.125
    for (int i = t; i < BR * HD_ / 4; i += 256) {
        int r  = i >> 4;
        int c4 = (i & 15) * 4;
        float4 qv = *(const float4*)&Q[(rowbase + r) * HID_ + h * HD_ + c4];
        qv.x *= 0.125f; qv.y *= 0.125f; qv.z *= 0.125f; qv.w *= 0.125f;
        *(float4*)&Qs[r][c4] = qv;
    }

    float m_i[4];
    float4 o[4];
#pragma unroll
    for (int i = 0; i < 4; i++) {
        m_i[i] = -1e30f;
        o[i] = make_float4(0.f, 0.f, 0.f, 0.f);
    }

    for (int j0 = 0; j0 < S_; j0 += BC) {
        __syncthreads();   // protect smem reuse from previous iteration reads
        // Load K (transposed) and V tiles
        for (int i = t; i < BC * HD_ / 4; i += 256) {
            int r  = i >> 4;
            int c4 = (i & 15) * 4;
            const size_t g = (size_t)(b * S_ + j0 + r) * HID_ + h * HD_ + c4;
            float4 kv = *(const float4*)&K[g];
            KsT[c4 + 0][r] = kv.x; KsT[c4 + 1][r] = kv.y;
            KsT[c4 + 2][r] = kv.z; KsT[c4 + 3][r] = kv.w;
            *(float4*)&Vs[r][c4] = *(const float4*)&V[g];
        }
        __syncthreads();

        // S = Qs @ KsT : rows ty*4+i, cols tx*2+j
        float s[4][2];
#pragma unroll
        for (int i = 0; i < 4; i++) { s[i][0] = 0.f; s[i][1] = 0.f; }

#pragma unroll
        for (int d = 0; d < HD_; d += 4) {
            float4 qa[4];
#pragma unroll
            for (int i = 0; i < 4; i++)
                qa[i] = *(const float4*)&Qs[ty * 4 + i][d];
            float kb0[2], kb1[2], kb2[2], kb3[2];
#pragma unroll
            for (int j = 0; j < 2; j++) {
                kb0[j] = KsT[d + 0][tx * 2 + j];
                kb1[j] = KsT[d + 1][tx * 2 + j];
                kb2[j] = KsT[d + 2][tx * 2 + j];
                kb3[j] = KsT[d + 3][tx * 2 + j];
            }
#pragma unroll
            for (int i = 0; i < 4; i++)
#pragma unroll
                for (int j = 0; j < 2; j++) {
                    s[i][j] += qa[i].x * kb0[j];
                    s[i][j] += qa[i].y * kb1[j];
                    s[i][j] += qa[i].z * kb2[j];
                    s[i][j] += qa[i].w * kb3[j];
                }
        }

        // additive mask
        float madd[2];
#pragma unroll
        for (int j = 0; j < 2; j++)
            madd[j] = (1.0f - mask[b * S_ + j0 + tx * 2 + j]) * (-10000.0f);
#pragma unroll
        for (int i = 0; i < 4; i++) { s[i][0] += madd[0]; s[i][1] += madd[1]; }

        // running rowmax + rescale + P = exp(s - m_new)
#pragma unroll
        for (int i = 0; i < 4; i++) {
            float rm = fmaxf(s[i][0], s[i][1]);
            rm = fmaxf(rm, __shfl_xor_sync(0xffffffffu, rm, 1));
            rm = fmaxf(rm, __shfl_xor_sync(0xffffffffu, rm, 2));
            rm = fmaxf(rm, __shfl_xor_sync(0xffffffffu, rm, 4));
            rm = fmaxf(rm, __shfl_xor_sync(0xffffffffu, rm, 8));
            float mn = fmaxf(m_i[i], rm);
            float sc = __expf(m_i[i] - mn);
            o[i].x *= sc; o[i].y *= sc; o[i].z *= sc; o[i].w *= sc;
            Ps[ty * 4 + i][tx * 2 + 0] = __expf(s[i][0] - mn);
            Ps[ty * 4 + i][tx * 2 + 1] = __expf(s[i][1] - mn);
            m_i[i] = mn;
        }
        __syncthreads();

        // O += P @ V : dims tx*4..tx*4+3
#pragma unroll
        for (int tt = 0; tt < BC; tt += 4) {
            float4 vv0 = *(const float4*)&Vs[tt + 0][tx * 4];
            float4 vv1 = *(const float4*)&Vs[tt + 1][tx * 4];
            float4 vv2 = *(const float4*)&Vs[tt + 2][tx * 4];
            float4 vv3 = *(const float4*)&Vs[tt + 3][tx * 4];
#pragma unroll
            for (int i = 0; i < 4; i++) {
                float4 pr = *(const float4*)&Ps[ty * 4 + i][tt];
                o[i].x += pr.x * vv0.x + pr.y * vv1.x + pr.z * vv2.x + pr.w * vv3.x;
                o[i].y += pr.x * vv0.y + pr.y * vv1.y + pr.z * vv2.y + pr.w * vv3.y;
                o[i].z += pr.x * vv0.z + pr.y * vv1.z + pr.z * vv2.z + pr.w * vv3.z;
                o[i].w += pr.x * vv0.w + pr.y * vv1.w + pr.z * vv2.w + pr.w * vv3.w;
            }
        }
    }

    const float ig = 1.0f / gamma[0];
#pragma unroll
    for (int i = 0; i < 4; i++) {
        float4 r = o[i];
        r.x *= ig; r.y *= ig; r.z *= ig; r.w *= ig;
        *(float4*)&Ctx[(rowbase + ty * 4 + i) * HID_ + h * HD_ + tx * 4] = r;
    }
}

// ============================================================
// Launch
// ============================================================
extern "C" void kernel_launch(void* const* d_in, const int* in_sizes, int n_in,
                              void* d_out, int out_size)
{
    (void)in_sizes; (void)n_in; (void)out_size;
    const float* X    = (const float*)d_in[0];
    const float* mask = (const float*)d_in[1];
    const float* Wq   = (const float*)d_in[2];
    const float* bq   = (const float*)d_in[3];
    const float* Wk   = (const float*)d_in[4];
    const float* bk   = (const float*)d_in[5];
    const float* Wv   = (const float*)d_in[6];
    const float* bv   = (const float*)d_in[7];
    const float* Wo   = (const float*)d_in[8];
    const float* bo   = (const float*)d_in[9];
    // d_in[10] = beta (cancels exactly in ConsMax shift)
    const float* gamma = (const float*)d_in[11];
    float* out = (float*)d_out;

    float *qp, *kp, *vp, *cp;
    cudaGetSymbolAddress((void**)&qp, g_Q);
    cudaGetSymbolAddress((void**)&kp, g_K);
    cudaGetSymbolAddress((void**)&vp, g_V);
    cudaGetSymbolAddress((void**)&cp, g_C);

    dim3 gg(HID_ / BN, MTOT / BM);   // (8, 32)
    sgemm_bias<<<gg, 256>>>(X, Wq, bq, qp, MTOT, HID_, HID_);
    sgemm_bias<<<gg, 256>>>(X, Wk, bk, kp, MTOT, HID_, HID_);
    sgemm_bias<<<gg, 256>>>(X, Wv, bv, vp, MTOT, HID_, HID_);

    dim3 ga(S_ / BR, NH_, B_);       // (32, 16, 2)
    consmax_attn<<<ga, 256>>>(qp, kp, vp, mask, gamma, cp);

    sgemm_bias<<<gg, 256>>>(cp, Wo, bo, out, MTOT, HID_, HID_);
}

// round 3
// speedup vs baseline: 1.2880x; 1.2880x over previous
#include <cuda_runtime.h>
#include <cuda_bf16.h>
#include <math.h>
#include <stdint.h>

#define B_    2
#define S_    2048
#define HID_  1024
#define NH_   16
#define HD_   64
#define MTOT  (B_ * S_)

// ---------------- scratch (static device allocations) ----------------
__device__ float g_Q[MTOT * HID_];
__device__ float g_K[MTOT * HID_];
__device__ float g_V[MTOT * HID_];
__device__ float g_C[MTOT * HID_];
__device__ __nv_bfloat16 g_Xhi[MTOT * HID_];
__device__ __nv_bfloat16 g_Xlo[MTOT * HID_];
__device__ __nv_bfloat16 g_Chi[MTOT * HID_];
__device__ __nv_bfloat16 g_Clo[MTOT * HID_];
__device__ __nv_bfloat16 g_Whi[4 * HID_ * HID_];
__device__ __nv_bfloat16 g_Wlo[4 * HID_ * HID_];

// ---------------- warp-MMA helpers (baseline PTX, no 'a' features) ----------------
__device__ __forceinline__ uint32_t smem_u32(const void* p) {
    uint32_t a;
    asm("{ .reg .u64 t; cvta.to.shared.u64 t, %1; cvt.u32.u64 %0, t; }" : "=r"(a) : "l"(p));
    return a;
}
__device__ __forceinline__ void ldsm_x4(uint32_t addr, uint32_t& r0, uint32_t& r1,
                                        uint32_t& r2, uint32_t& r3) {
    asm volatile("ldmatrix.sync.aligned.m8n8.x4.shared.b16 {%0,%1,%2,%3}, [%4];"
                 : "=r"(r0), "=r"(r1), "=r"(r2), "=r"(r3) : "r"(addr));
}
__device__ __forceinline__ void mma16816(float* c, uint32_t a0, uint32_t a1,
                                         uint32_t a2, uint32_t a3,
                                         uint32_t b0, uint32_t b1) {
    asm volatile(
        "mma.sync.aligned.m16n8k16.row.col.f32.bf16.bf16.f32 "
        "{%0,%1,%2,%3}, {%4,%5,%6,%7}, {%8,%9}, {%0,%1,%2,%3};"
        : "+f"(c[0]), "+f"(c[1]), "+f"(c[2]), "+f"(c[3])
        : "r"(a0), "r"(a1), "r"(a2), "r"(a3), "r"(b0), "r"(b1));
}

// ---------------- fp32 -> bf16 hi/lo split ----------------
__global__ __launch_bounds__(256) void cvt_split(
    const float* __restrict__ in, __nv_bfloat16* __restrict__ hi,
    __nv_bfloat16* __restrict__ lo, int n4)
{
    int i = blockIdx.x * blockDim.x + threadIdx.x;
    if (i >= n4) return;
    float4 v = ((const float4*)in)[i];
    float x[4] = {v.x, v.y, v.z, v.w};
    __nv_bfloat16 h[4], l[4];
#pragma unroll
    for (int j = 0; j < 4; j++) {
        h[j] = __float2bfloat16(x[j]);
        l[j] = __float2bfloat16(x[j] - __bfloat162float(h[j]));
    }
    ((ushort4*)hi)[i] = make_ushort4(*(unsigned short*)&h[0], *(unsigned short*)&h[1],
                                     *(unsigned short*)&h[2], *(unsigned short*)&h[3]);
    ((ushort4*)lo)[i] = make_ushort4(*(unsigned short*)&l[0], *(unsigned short*)&l[1],
                                     *(unsigned short*)&l[2], *(unsigned short*)&l[3]);
}

// ============================================================
// Tensor-core GEMM: C[M,N] = A[M,K] @ W[N,K]^T + bias
// bf16 hi/lo 3-MMA emulation (fp32-grade accuracy).
// CTA tile 128x128, BK=32, 8 warps (2x4), warp tile 64x32.
// ============================================================
#define LDA 40   // padded bf16 row stride (80B: 5 x 16B units, coprime with 8 -> no ldmatrix conflicts)

__global__ __launch_bounds__(256) void gemm_mma_bf16x3(
    const __nv_bfloat16* __restrict__ Ahi, const __nv_bfloat16* __restrict__ Alo,
    const __nv_bfloat16* __restrict__ Bhi, const __nv_bfloat16* __restrict__ Blo,
    const float* __restrict__ bias, float* __restrict__ C,
    int M, int N, int K)
{
    __shared__ __nv_bfloat16 sAhi[128 * LDA];
    __shared__ __nv_bfloat16 sAlo[128 * LDA];
    __shared__ __nv_bfloat16 sBhi[128 * LDA];
    __shared__ __nv_bfloat16 sBlo[128 * LDA];

    const int t    = threadIdx.x;
    const int lane = t & 31;
    const int wid  = t >> 5;
    const int wm   = (wid & 1) * 64;   // warp M origin in tile
    const int wn   = (wid >> 1) * 32;  // warp N origin in tile
    const int bm   = blockIdx.y * 128;
    const int bn   = blockIdx.x * 128;

    float acc[4][4][4];
#pragma unroll
    for (int i = 0; i < 4; i++)
#pragma unroll
        for (int j = 0; j < 4; j++)
#pragma unroll
            for (int r = 0; r < 4; r++) acc[i][j][r] = 0.0f;

    // per-thread load coords: 2 row-batches x 1 col chunk
    const int lr = t >> 2;        // 0..63
    const int lc = (t & 3) * 8;   // 0,8,16,24

    // ldmatrix smem addresses (byte)
    const uint32_t aBase = smem_u32(sAhi);
    const uint32_t alBase = smem_u32(sAlo);
    const uint32_t bBase = smem_u32(sBhi);
    const uint32_t blBase = smem_u32(sBlo);
    const uint32_t aOff = (uint32_t)(((wm + (lane & 15)) * LDA + (lane >> 4) * 8) * 2);
    const uint32_t bOff = (uint32_t)(((wn + (lane >> 4) * 8 + (lane & 7)) * LDA + ((lane >> 3) & 1) * 8) * 2);

    for (int k0 = 0; k0 < K; k0 += 32) {
        __syncthreads();
#pragma unroll
        for (int bch = 0; bch < 2; bch++) {
            int r = lr + bch * 64;
            size_t ga = (size_t)(bm + r) * K + k0 + lc;
            size_t gb = (size_t)(bn + r) * K + k0 + lc;
            *(uint4*)&sAhi[r * LDA + lc] = *(const uint4*)(Ahi + ga);
            *(uint4*)&sAlo[r * LDA + lc] = *(const uint4*)(Alo + ga);
            *(uint4*)&sBhi[r * LDA + lc] = *(const uint4*)(Bhi + gb);
            *(uint4*)&sBlo[r * LDA + lc] = *(const uint4*)(Blo + gb);
        }
        __syncthreads();

#pragma unroll
        for (int ks = 0; ks < 2; ks++) {
            const uint32_t kb = ks * 32;  // 16 bf16 = 32 bytes
            // B fragments: 2 x4-ldmatrix cover 4 n-tiles (hi), 2 more (lo)
            uint32_t bh[8], bl[8];
#pragma unroll
            for (int pr = 0; pr < 2; pr++) {
                uint32_t ba = bOff + (uint32_t)(pr * 16 * LDA * 2) + kb;
                ldsm_x4(bBase + ba,  bh[pr*4+0], bh[pr*4+1], bh[pr*4+2], bh[pr*4+3]);
                ldsm_x4(blBase + ba, bl[pr*4+0], bl[pr*4+1], bl[pr*4+2], bl[pr*4+3]);
            }
            // A fragments per m-tile (hi & lo), then 3-term MMA
            uint32_t ah[4][4], al[4][4];
#pragma unroll
            for (int mt = 0; mt < 4; mt++) {
                uint32_t aa = aOff + (uint32_t)(mt * 16 * LDA * 2) + kb;
                ldsm_x4(aBase + aa,  ah[mt][0], ah[mt][1], ah[mt][2], ah[mt][3]);
                ldsm_x4(alBase + aa, al[mt][0], al[mt][1], al[mt][2], al[mt][3]);
            }
#pragma unroll
            for (int mt = 0; mt < 4; mt++) {
#pragma unroll
                for (int nt = 0; nt < 4; nt++) {
                    const int pr = nt >> 1, hf = (nt & 1) * 2;
                    uint32_t b0h = bh[pr*4 + hf], b1h = bh[pr*4 + hf + 1];
                    uint32_t b0l = bl[pr*4 + hf], b1l = bl[pr*4 + hf + 1];
                    mma16816(acc[mt][nt], ah[mt][0], ah[mt][1], ah[mt][2], ah[mt][3], b0h, b1h);
                    mma16816(acc[mt][nt], al[mt][0], al[mt][1], al[mt][2], al[mt][3], b0h, b1h);
                    mma16816(acc[mt][nt], ah[mt][0], ah[mt][1], ah[mt][2], ah[mt][3], b0l, b1l);
                }
            }
        }
    }

    // epilogue: c0,c1 -> (row, col..col+1); c2,c3 -> (row+8, col..col+1)
#pragma unroll
    for (int mt = 0; mt < 4; mt++) {
#pragma unroll
        for (int nt = 0; nt < 4; nt++) {
            int row = bm + wm + mt * 16 + (lane >> 2);
            int col = bn + wn + nt * 8 + (lane & 3) * 2;
            float2 bvv = *(const float2*)&bias[col];
            float2 v0 = make_float2(acc[mt][nt][0] + bvv.x, acc[mt][nt][1] + bvv.y);
            float2 v1 = make_float2(acc[mt][nt][2] + bvv.x, acc[mt][nt][3] + bvv.y);
            *(float2*)&C[(size_t)row * N + col] = v0;
            *(float2*)&C[(size_t)(row + 8) * N + col] = v1;
        }
    }
}

// ============================================================
// Flash-style ConsMax attention (fp32, unchanged).
// ============================================================
#define BR 64
#define BC 32

__global__ __launch_bounds__(256) void consmax_attn(
    const float* __restrict__ Q, const float* __restrict__ K,
    const float* __restrict__ V, const float* __restrict__ mask,
    const float* __restrict__ gamma, float* __restrict__ Ctx)
{
    __shared__ float Qs[BR][HD_];
    __shared__ float KsT[HD_][BC + 1];
    __shared__ float Vs[BC][HD_];
    __shared__ float Ps[BR][BC];

    const int qb = blockIdx.x;
    const int h  = blockIdx.y;
    const int b  = blockIdx.z;
    const int t  = threadIdx.x;
    const int tx = t & 15;
    const int ty = t >> 4;

    const size_t rowbase = (size_t)(b * S_ + qb * BR);

    for (int i = t; i < BR * HD_ / 4; i += 256) {
        int r  = i >> 4;
        int c4 = (i & 15) * 4;
        float4 qv = *(const float4*)&Q[(rowbase + r) * HID_ + h * HD_ + c4];
        qv.x *= 0.125f; qv.y *= 0.125f; qv.z *= 0.125f; qv.w *= 0.125f;
        *(float4*)&Qs[r][c4] = qv;
    }

    float m_i[4];
    float4 o[4];
#pragma unroll
    for (int i = 0; i < 4; i++) {
        m_i[i] = -1e30f;
        o[i] = make_float4(0.f, 0.f, 0.f, 0.f);
    }

    for (int j0 = 0; j0 < S_; j0 += BC) {
        __syncthreads();
        for (int i = t; i < BC * HD_ / 4; i += 256) {
            int r  = i >> 4;
            int c4 = (i & 15) * 4;
            const size_t g = (size_t)(b * S_ + j0 + r) * HID_ + h * HD_ + c4;
            float4 kv = *(const float4*)&K[g];
            KsT[c4 + 0][r] = kv.x; KsT[c4 + 1][r] = kv.y;
            KsT[c4 + 2][r] = kv.z; KsT[c4 + 3][r] = kv.w;
            *(float4*)&Vs[r][c4] = *(const float4*)&V[g];
        }
        __syncthreads();

        float s[4][2];
#pragma unroll
        for (int i = 0; i < 4; i++) { s[i][0] = 0.f; s[i][1] = 0.f; }

#pragma unroll
        for (int d = 0; d < HD_; d += 4) {
            float4 qa[4];
#pragma unroll
            for (int i = 0; i < 4; i++)
                qa[i] = *(const float4*)&Qs[ty * 4 + i][d];
            float kb0[2], kb1[2], kb2[2], kb3[2];
#pragma unroll
            for (int j = 0; j < 2; j++) {
                kb0[j] = KsT[d + 0][tx * 2 + j];
                kb1[j] = KsT[d + 1][tx * 2 + j];
                kb2[j] = KsT[d + 2][tx * 2 + j];
                kb3[j] = KsT[d + 3][tx * 2 + j];
            }
#pragma unroll
            for (int i = 0; i < 4; i++)
#pragma unroll
                for (int j = 0; j < 2; j++) {
                    s[i][j] += qa[i].x * kb0[j];
                    s[i][j] += qa[i].y * kb1[j];
                    s[i][j] += qa[i].z * kb2[j];
                    s[i][j] += qa[i].w * kb3[j];
                }
        }

        float madd[2];
#pragma unroll
        for (int j = 0; j < 2; j++)
            madd[j] = (1.0f - mask[b * S_ + j0 + tx * 2 + j]) * (-10000.0f);
#pragma unroll
        for (int i = 0; i < 4; i++) { s[i][0] += madd[0]; s[i][1] += madd[1]; }

#pragma unroll
        for (int i = 0; i < 4; i++) {
            float rm = fmaxf(s[i][0], s[i][1]);
            rm = fmaxf(rm, __shfl_xor_sync(0xffffffffu, rm, 1));
            rm = fmaxf(rm, __shfl_xor_sync(0xffffffffu, rm, 2));
            rm = fmaxf(rm, __shfl_xor_sync(0xffffffffu, rm, 4));
            rm = fmaxf(rm, __shfl_xor_sync(0xffffffffu, rm, 8));
            float mn = fmaxf(m_i[i], rm);
            float sc = __expf(m_i[i] - mn);
            o[i].x *= sc; o[i].y *= sc; o[i].z *= sc; o[i].w *= sc;
            Ps[ty * 4 + i][tx * 2 + 0] = __expf(s[i][0] - mn);
            Ps[ty * 4 + i][tx * 2 + 1] = __expf(s[i][1] - mn);
            m_i[i] = mn;
        }
        __syncthreads();

#pragma unroll
        for (int tt = 0; tt < BC; tt += 4) {
            float4 vv0 = *(const float4*)&Vs[tt + 0][tx * 4];
            float4 vv1 = *(const float4*)&Vs[tt + 1][tx * 4];
            float4 vv2 = *(const float4*)&Vs[tt + 2][tx * 4];
            float4 vv3 = *(const float4*)&Vs[tt + 3][tx * 4];
#pragma unroll
            for (int i = 0; i < 4; i++) {
                float4 pr = *(const float4*)&Ps[ty * 4 + i][tt];
                o[i].x += pr.x * vv0.x + pr.y * vv1.x + pr.z * vv2.x + pr.w * vv3.x;
                o[i].y += pr.x * vv0.y + pr.y * vv1.y + pr.z * vv2.y + pr.w * vv3.y;
                o[i].z += pr.x * vv0.z + pr.y * vv1.z + pr.z * vv2.z + pr.w * vv3.z;
                o[i].w += pr.x * vv0.w + pr.y * vv1.w + pr.z * vv2.w + pr.w * vv3.w;
            }
        }
    }

    const float ig = 1.0f / gamma[0];
#pragma unroll
    for (int i = 0; i < 4; i++) {
        float4 r = o[i];
        r.x *= ig; r.y *= ig; r.z *= ig; r.w *= ig;
        *(float4*)&Ctx[(rowbase + ty * 4 + i) * HID_ + h * HD_ + tx * 4] = r;
    }
}

// ============================================================
// Launch
// ============================================================
extern "C" void kernel_launch(void* const* d_in, const int* in_sizes, int n_in,
                              void* d_out, int out_size)
{
    (void)in_sizes; (void)n_in; (void)out_size;
    const float* X    = (const float*)d_in[0];
    const float* mask = (const float*)d_in[1];
    const float* Wq   = (const float*)d_in[2];
    const float* bq   = (const float*)d_in[3];
    const float* Wk   = (const float*)d_in[4];
    const float* bk   = (const float*)d_in[5];
    const float* Wv   = (const float*)d_in[6];
    const float* bv   = (const float*)d_in[7];
    const float* Wo   = (const float*)d_in[8];
    const float* bo   = (const float*)d_in[9];
    const float* gamma = (const float*)d_in[11];   // beta (d_in[10]) cancels exactly
    float* out = (float*)d_out;

    float *qp, *kp, *vp, *cp;
    __nv_bfloat16 *xhi, *xlo, *chi, *clo, *whi, *wlo;
    cudaGetSymbolAddress((void**)&qp, g_Q);
    cudaGetSymbolAddress((void**)&kp, g_K);
    cudaGetSymbolAddress((void**)&vp, g_V);
    cudaGetSymbolAddress((void**)&cp, g_C);
    cudaGetSymbolAddress((void**)&xhi, g_Xhi);
    cudaGetSymbolAddress((void**)&xlo, g_Xlo);
    cudaGetSymbolAddress((void**)&chi, g_Chi);
    cudaGetSymbolAddress((void**)&clo, g_Clo);
    cudaGetSymbolAddress((void**)&whi, g_Whi);
    cudaGetSymbolAddress((void**)&wlo, g_Wlo);

    const int WN = HID_ * HID_;
    cvt_split<<<(MTOT * HID_ / 4 + 255) / 256, 256>>>(X,  xhi, xlo, MTOT * HID_ / 4);
    cvt_split<<<(WN / 4 + 255) / 256, 256>>>(Wq, whi + 0 * WN, wlo + 0 * WN, WN / 4);
    cvt_split<<<(WN / 4 + 255) / 256, 256>>>(Wk, whi + 1 * WN, wlo + 1 * WN, WN / 4);
    cvt_split<<<(WN / 4 + 255) / 256, 256>>>(Wv, whi + 2 * WN, wlo + 2 * WN, WN / 4);
    cvt_split<<<(WN / 4 + 255) / 256, 256>>>(Wo, whi + 3 * WN, wlo + 3 * WN, WN / 4);

    dim3 gg(HID_ / 128, MTOT / 128);      // (8, 32)
    gemm_mma_bf16x3<<<gg, 256>>>(xhi, xlo, whi + 0 * WN, wlo + 0 * WN, bq, qp, MTOT, HID_, HID_);
    gemm_mma_bf16x3<<<gg, 256>>>(xhi, xlo, whi + 1 * WN, wlo + 1 * WN, bk, kp, MTOT, HID_, HID_);
    gemm_mma_bf16x3<<<gg, 256>>>(xhi, xlo, whi + 2 * WN, wlo + 2 * WN, bv, vp, MTOT, HID_, HID_);

    dim3 ga(S_ / BR, NH_, B_);            // (32, 16, 2)
    consmax_attn<<<ga, 256>>>(qp, kp, vp, mask, gamma, cp);

    cvt_split<<<(MTOT * HID_ / 4 + 255) / 256, 256>>>(cp, chi, clo, MTOT * HID_ / 4);
    gemm_mma_bf16x3<<<gg, 256>>>(chi, clo, whi + 3 * WN, wlo + 3 * WN, bo, out, MTOT, HID_, HID_);
}

// round 4
// speedup vs baseline: 2.2876x; 1.7761x over previous
#include <cuda_runtime.h>
#include <cuda_bf16.h>
#include <math.h>
#include <stdint.h>

#define B_    2
#define S_    2048
#define HID_  1024
#define NH_   16
#define HD_   64
#define MTOT  (B_ * S_)

// ---------------- scratch (static device allocations) ----------------
__device__ __nv_bfloat16 g_Xhi[MTOT * HID_];
__device__ __nv_bfloat16 g_Xlo[MTOT * HID_];
__device__ __nv_bfloat16 g_Whi[4 * HID_ * HID_];
__device__ __nv_bfloat16 g_Wlo[4 * HID_ * HID_];
__device__ __nv_bfloat16 g_Qh[MTOT * HID_];
__device__ __nv_bfloat16 g_Ql[MTOT * HID_];
__device__ __nv_bfloat16 g_Kh[MTOT * HID_];
__device__ __nv_bfloat16 g_Kl[MTOT * HID_];
__device__ __nv_bfloat16 g_Vh[MTOT * HID_];
__device__ __nv_bfloat16 g_Vl[MTOT * HID_];
__device__ __nv_bfloat16 g_Ch[MTOT * HID_];
__device__ __nv_bfloat16 g_Cl[MTOT * HID_];

// ---------------- warp-MMA helpers (baseline PTX only) ----------------
__device__ __forceinline__ uint32_t smem_u32(const void* p) {
    uint32_t a;
    asm("{ .reg .u64 t; cvta.to.shared.u64 t, %1; cvt.u32.u64 %0, t; }" : "=r"(a) : "l"(p));
    return a;
}
__device__ __forceinline__ void ldsm_x4(uint32_t addr, uint32_t& r0, uint32_t& r1,
                                        uint32_t& r2, uint32_t& r3) {
    asm volatile("ldmatrix.sync.aligned.m8n8.x4.shared.b16 {%0,%1,%2,%3}, [%4];"
                 : "=r"(r0), "=r"(r1), "=r"(r2), "=r"(r3) : "r"(addr));
}
__device__ __forceinline__ void ldsm_x4_trans(uint32_t addr, uint32_t& r0, uint32_t& r1,
                                              uint32_t& r2, uint32_t& r3) {
    asm volatile("ldmatrix.sync.aligned.m8n8.x4.trans.shared.b16 {%0,%1,%2,%3}, [%4];"
                 : "=r"(r0), "=r"(r1), "=r"(r2), "=r"(r3) : "r"(addr));
}
__device__ __forceinline__ void mma16816(float* c, uint32_t a0, uint32_t a1,
                                         uint32_t a2, uint32_t a3,
                                         uint32_t b0, uint32_t b1) {
    asm volatile(
        "mma.sync.aligned.m16n8k16.row.col.f32.bf16.bf16.f32 "
        "{%0,%1,%2,%3}, {%4,%5,%6,%7}, {%8,%9}, {%0,%1,%2,%3};"
        : "+f"(c[0]), "+f"(c[1]), "+f"(c[2]), "+f"(c[3])
        : "r"(a0), "r"(a1), "r"(a2), "r"(a3), "r"(b0), "r"(b1));
}
__device__ __forceinline__ void pack2_hilo(float a, float b, uint32_t& hi, uint32_t& lo) {
    __nv_bfloat16 ah = __float2bfloat16(a), bh = __float2bfloat16(b);
    float ar = a - __bfloat162float(ah), br = b - __bfloat162float(bh);
    __nv_bfloat16 al = __float2bfloat16(ar), bl = __float2bfloat16(br);
    hi = (uint32_t)(*(unsigned short*)&ah) | ((uint32_t)(*(unsigned short*)&bh) << 16);
    lo = (uint32_t)(*(unsigned short*)&al) | ((uint32_t)(*(unsigned short*)&bl) << 16);
}

// ---------------- fp32 -> bf16 hi/lo split ----------------
__global__ __launch_bounds__(256) void cvt_split(
    const float* __restrict__ in, __nv_bfloat16* __restrict__ hi,
    __nv_bfloat16* __restrict__ lo, int n4)
{
    int i = blockIdx.x * blockDim.x + threadIdx.x;
    if (i >= n4) return;
    float4 v = ((const float4*)in)[i];
    float x[4] = {v.x, v.y, v.z, v.w};
    __nv_bfloat16 h[4], l[4];
#pragma unroll
    for (int j = 0; j < 4; j++) {
        h[j] = __float2bfloat16(x[j]);
        l[j] = __float2bfloat16(x[j] - __bfloat162float(h[j]));
    }
    ((ushort4*)hi)[i] = make_ushort4(*(unsigned short*)&h[0], *(unsigned short*)&h[1],
                                     *(unsigned short*)&h[2], *(unsigned short*)&h[3]);
    ((ushort4*)lo)[i] = make_ushort4(*(unsigned short*)&l[0], *(unsigned short*)&l[1],
                                     *(unsigned short*)&l[2], *(unsigned short*)&l[3]);
}

// ============================================================
// Tensor-core GEMM: C[M,N] = A[M,K] @ W[N,K]^T + bias
// bf16 hi/lo 3-MMA; OUT16: emit bf16 hi/lo pair instead of fp32.
// ============================================================
#define LDA 40

template<bool OUT16>
__global__ __launch_bounds__(256) void gemm_mma_bf16x3(
    const __nv_bfloat16* __restrict__ Ahi, const __nv_bfloat16* __restrict__ Alo,
    const __nv_bfloat16* __restrict__ Bhi, const __nv_bfloat16* __restrict__ Blo,
    const float* __restrict__ bias, float* __restrict__ C,
    __nv_bfloat16* __restrict__ Ch, __nv_bfloat16* __restrict__ Cl,
    int M, int N, int K)
{
    __shared__ __nv_bfloat16 sAhi[128 * LDA];
    __shared__ __nv_bfloat16 sAlo[128 * LDA];
    __shared__ __nv_bfloat16 sBhi[128 * LDA];
    __shared__ __nv_bfloat16 sBlo[128 * LDA];

    const int t    = threadIdx.x;
    const int lane = t & 31;
    const int wid  = t >> 5;
    const int wm   = (wid & 1) * 64;
    const int wn   = (wid >> 1) * 32;
    const int bm   = blockIdx.y * 128;
    const int bn   = blockIdx.x * 128;

    float acc[4][4][4];
#pragma unroll
    for (int i = 0; i < 4; i++)
#pragma unroll
        for (int j = 0; j < 4; j++)
#pragma unroll
            for (int r = 0; r < 4; r++) acc[i][j][r] = 0.0f;

    const int lr = t >> 2;
    const int lc = (t & 3) * 8;

    const uint32_t aBase  = smem_u32(sAhi);
    const uint32_t alBase = smem_u32(sAlo);
    const uint32_t bBase  = smem_u32(sBhi);
    const uint32_t blBase = smem_u32(sBlo);
    const uint32_t aOff = (uint32_t)(((wm + (lane & 15)) * LDA + (lane >> 4) * 8) * 2);
    const uint32_t bOff = (uint32_t)(((wn + (lane >> 4) * 8 + (lane & 7)) * LDA + ((lane >> 3) & 1) * 8) * 2);

    for (int k0 = 0; k0 < K; k0 += 32) {
        __syncthreads();
#pragma unroll
        for (int bch = 0; bch < 2; bch++) {
            int r = lr + bch * 64;
            size_t ga = (size_t)(bm + r) * K + k0 + lc;
            size_t gb = (size_t)(bn + r) * K + k0 + lc;
            *(uint4*)&sAhi[r * LDA + lc] = *(const uint4*)(Ahi + ga);
            *(uint4*)&sAlo[r * LDA + lc] = *(const uint4*)(Alo + ga);
            *(uint4*)&sBhi[r * LDA + lc] = *(const uint4*)(Bhi + gb);
            *(uint4*)&sBlo[r * LDA + lc] = *(const uint4*)(Blo + gb);
        }
        __syncthreads();

#pragma unroll
        for (int ks = 0; ks < 2; ks++) {
            const uint32_t kb = ks * 32;
            uint32_t bh[8], bl[8];
#pragma unroll
            for (int pr = 0; pr < 2; pr++) {
                uint32_t ba = bOff + (uint32_t)(pr * 16 * LDA * 2) + kb;
                ldsm_x4(bBase + ba,  bh[pr*4+0], bh[pr*4+1], bh[pr*4+2], bh[pr*4+3]);
                ldsm_x4(blBase + ba, bl[pr*4+0], bl[pr*4+1], bl[pr*4+2], bl[pr*4+3]);
            }
            uint32_t ah[4][4], al[4][4];
#pragma unroll
            for (int mt = 0; mt < 4; mt++) {
                uint32_t aa = aOff + (uint32_t)(mt * 16 * LDA * 2) + kb;
                ldsm_x4(aBase + aa,  ah[mt][0], ah[mt][1], ah[mt][2], ah[mt][3]);
                ldsm_x4(alBase + aa, al[mt][0], al[mt][1], al[mt][2], al[mt][3]);
            }
#pragma unroll
            for (int mt = 0; mt < 4; mt++) {
#pragma unroll
                for (int nt = 0; nt < 4; nt++) {
                    const int pr = nt >> 1, hf = (nt & 1) * 2;
                    uint32_t b0h = bh[pr*4 + hf], b1h = bh[pr*4 + hf + 1];
                    uint32_t b0l = bl[pr*4 + hf], b1l = bl[pr*4 + hf + 1];
                    mma16816(acc[mt][nt], ah[mt][0], ah[mt][1], ah[mt][2], ah[mt][3], b0h, b1h);
                    mma16816(acc[mt][nt], al[mt][0], al[mt][1], al[mt][2], al[mt][3], b0h, b1h);
                    mma16816(acc[mt][nt], ah[mt][0], ah[mt][1], ah[mt][2], ah[mt][3], b0l, b1l);
                }
            }
        }
    }

#pragma unroll
    for (int mt = 0; mt < 4; mt++) {
#pragma unroll
        for (int nt = 0; nt < 4; nt++) {
            int row = bm + wm + mt * 16 + (lane >> 2);
            int col = bn + wn + nt * 8 + (lane & 3) * 2;
            float2 bvv = *(const float2*)&bias[col];
            float v0x = acc[mt][nt][0] + bvv.x, v0y = acc[mt][nt][1] + bvv.y;
            float v1x = acc[mt][nt][2] + bvv.x, v1y = acc[mt][nt][3] + bvv.y;
            if (OUT16) {
                uint32_t h0, l0, h1, l1;
                pack2_hilo(v0x, v0y, h0, l0);
                pack2_hilo(v1x, v1y, h1, l1);
                *(uint32_t*)&Ch[(size_t)row * N + col] = h0;
                *(uint32_t*)&Cl[(size_t)row * N + col] = l0;
                *(uint32_t*)&Ch[(size_t)(row + 8) * N + col] = h1;
                *(uint32_t*)&Cl[(size_t)(row + 8) * N + col] = l1;
            } else {
                *(float2*)&C[(size_t)row * N + col] = make_float2(v0x, v0y);
                *(float2*)&C[(size_t)(row + 8) * N + col] = make_float2(v1x, v1y);
            }
        }
    }
}

// ============================================================
// Tensor-core flash ConsMax attention.
// 64 q-rows/CTA (4 warps x 16 rows), Bc=64 keys/chunk.
// QK^T and PV both bf16 hi/lo 3-MMA. S->P repack in registers.
// ============================================================
#define LDV 72

__global__ __launch_bounds__(128) void consmax_attn_mma(
    const __nv_bfloat16* __restrict__ Qh, const __nv_bfloat16* __restrict__ Ql,
    const __nv_bfloat16* __restrict__ Kh, const __nv_bfloat16* __restrict__ Kl,
    const __nv_bfloat16* __restrict__ Vh, const __nv_bfloat16* __restrict__ Vl,
    const float* __restrict__ mask, const float* __restrict__ gamma,
    __nv_bfloat16* __restrict__ Ch, __nv_bfloat16* __restrict__ Cl)
{
    __shared__ __nv_bfloat16 sKh[64 * LDV], sKl[64 * LDV];
    __shared__ __nv_bfloat16 sVh[64 * LDV], sVl[64 * LDV];
    __shared__ float smask[64];

    const int qb = blockIdx.x, h = blockIdx.y, b = blockIdx.z;
    const int t = threadIdx.x, lane = t & 31, w = t >> 5;
    const int row0 = b * S_ + qb * 64;

    const uint32_t khB = smem_u32(sKh), klB = smem_u32(sKl);
    const uint32_t vhB = smem_u32(sVh), vlB = smem_u32(sVl);

    // ---- stage Q tile through K smem, ldmatrix into registers ----
    {
        int r = t >> 1, half = t & 1;
        const size_t g = (size_t)(row0 + r) * HID_ + h * HD_ + half * 32;
        int so = r * LDV + half * 32;
#pragma unroll
        for (int i = 0; i < 4; i++) {
            *(uint4*)&sKh[so + i * 8] = *(const uint4*)(Qh + g + i * 8);
            *(uint4*)&sKl[so + i * 8] = *(const uint4*)(Ql + g + i * 8);
        }
    }
    __syncthreads();
    uint32_t qh[4][4], ql[4][4];
#pragma unroll
    for (int ks = 0; ks < 4; ks++) {
        uint32_t addr = (uint32_t)(((w * 16 + (lane & 15)) * LDV + ks * 16 + (lane >> 4) * 8) * 2);
        ldsm_x4(khB + addr, qh[ks][0], qh[ks][1], qh[ks][2], qh[ks][3]);
        ldsm_x4(klB + addr, ql[ks][0], ql[ks][1], ql[ks][2], ql[ks][3]);
    }
    __syncthreads();

    float m0 = -1e30f, m1 = -1e30f;
    float O[8][4];
#pragma unroll
    for (int nt = 0; nt < 8; nt++)
#pragma unroll
        for (int r = 0; r < 4; r++) O[nt][r] = 0.0f;

    for (int j0 = 0; j0 < S_; j0 += 64) {
        // ---- load K/V chunk ----
        {
            int r = t >> 1, half = t & 1;
            const size_t g = (size_t)(b * S_ + j0 + r) * HID_ + h * HD_ + half * 32;
            int so = r * LDV + half * 32;
#pragma unroll
            for (int i = 0; i < 4; i++) {
                *(uint4*)&sKh[so + i * 8] = *(const uint4*)(Kh + g + i * 8);
                *(uint4*)&sKl[so + i * 8] = *(const uint4*)(Kl + g + i * 8);
                *(uint4*)&sVh[so + i * 8] = *(const uint4*)(Vh + g + i * 8);
                *(uint4*)&sVl[so + i * 8] = *(const uint4*)(Vl + g + i * 8);
            }
            if (t < 64) smask[t] = (1.0f - mask[b * S_ + j0 + t]) * (-10000.0f);
        }
        __syncthreads();

        // ---- S = Q K^T (3-MMA hi/lo) ----
        float sc[8][4];
#pragma unroll
        for (int nt = 0; nt < 8; nt++)
#pragma unroll
            for (int r = 0; r < 4; r++) sc[nt][r] = 0.0f;

#pragma unroll
        for (int ks = 0; ks < 4; ks++) {
            uint32_t bh[4][4], bl[4][4];
#pragma unroll
            for (int nb = 0; nb < 4; nb++) {
                uint32_t addr = (uint32_t)(((nb * 16 + (lane >> 4) * 8 + (lane & 7)) * LDV
                                            + ks * 16 + ((lane >> 3) & 1) * 8) * 2);
                ldsm_x4(khB + addr, bh[nb][0], bh[nb][1], bh[nb][2], bh[nb][3]);
                ldsm_x4(klB + addr, bl[nb][0], bl[nb][1], bl[nb][2], bl[nb][3]);
            }
#pragma unroll
            for (int nb = 0; nb < 4; nb++) {
                mma16816(sc[2*nb],   qh[ks][0], qh[ks][1], qh[ks][2], qh[ks][3], bh[nb][0], bh[nb][1]);
                mma16816(sc[2*nb],   ql[ks][0], ql[ks][1], ql[ks][2], ql[ks][3], bh[nb][0], bh[nb][1]);
                mma16816(sc[2*nb],   qh[ks][0], qh[ks][1], qh[ks][2], qh[ks][3], bl[nb][0], bl[nb][1]);
                mma16816(sc[2*nb+1], qh[ks][0], qh[ks][1], qh[ks][2], qh[ks][3], bh[nb][2], bh[nb][3]);
                mma16816(sc[2*nb+1], ql[ks][0], ql[ks][1], ql[ks][2], ql[ks][3], bh[nb][2], bh[nb][3]);
                mma16816(sc[2*nb+1], qh[ks][0], qh[ks][1], qh[ks][2], qh[ks][3], bl[nb][2], bl[nb][3]);
            }
        }

        // ---- scale + mask + running rowmax ----
        float mn0 = m0, mn1 = m1;
#pragma unroll
        for (int nt = 0; nt < 8; nt++) {
            int col = nt * 8 + (lane & 3) * 2;
            float ma = smask[col], mb2 = smask[col + 1];
            sc[nt][0] = fmaf(sc[nt][0], 0.125f, ma);
            sc[nt][1] = fmaf(sc[nt][1], 0.125f, mb2);
            sc[nt][2] = fmaf(sc[nt][2], 0.125f, ma);
            sc[nt][3] = fmaf(sc[nt][3], 0.125f, mb2);
            mn0 = fmaxf(mn0, fmaxf(sc[nt][0], sc[nt][1]));
            mn1 = fmaxf(mn1, fmaxf(sc[nt][2], sc[nt][3]));
        }
        mn0 = fmaxf(mn0, __shfl_xor_sync(0xffffffffu, mn0, 1));
        mn0 = fmaxf(mn0, __shfl_xor_sync(0xffffffffu, mn0, 2));
        mn1 = fmaxf(mn1, __shfl_xor_sync(0xffffffffu, mn1, 1));
        mn1 = fmaxf(mn1, __shfl_xor_sync(0xffffffffu, mn1, 2));
        float f0 = __expf(m0 - mn0), f1 = __expf(m1 - mn1);
        m0 = mn0; m1 = mn1;

        // ---- P = exp(s - m), hi/lo split, repack to A-frags ----
        uint32_t pah[4][4], pal[4][4];
#pragma unroll
        for (int ks = 0; ks < 4; ks++) {
            float p00 = __expf(sc[2*ks][0] - m0),   p01 = __expf(sc[2*ks][1] - m0);
            float p02 = __expf(sc[2*ks][2] - m1),   p03 = __expf(sc[2*ks][3] - m1);
            float p10 = __expf(sc[2*ks+1][0] - m0), p11 = __expf(sc[2*ks+1][1] - m0);
            float p12 = __expf(sc[2*ks+1][2] - m1), p13 = __expf(sc[2*ks+1][3] - m1);
            pack2_hilo(p00, p01, pah[ks][0], pal[ks][0]);
            pack2_hilo(p02, p03, pah[ks][1], pal[ks][1]);
            pack2_hilo(p10, p11, pah[ks][2], pal[ks][2]);
            pack2_hilo(p12, p13, pah[ks][3], pal[ks][3]);
        }

        // ---- rescale O ----
#pragma unroll
        for (int nt = 0; nt < 8; nt++) {
            O[nt][0] *= f0; O[nt][1] *= f0; O[nt][2] *= f1; O[nt][3] *= f1;
        }

        // ---- O += P V (3-MMA hi/lo) ----
#pragma unroll
        for (int ks = 0; ks < 4; ks++) {
            uint32_t vh[4][4], vl[4][4];
#pragma unroll
            for (int db = 0; db < 4; db++) {
                uint32_t addr = (uint32_t)(((ks * 16 + ((lane >> 3) & 1) * 8 + (lane & 7)) * LDV
                                            + db * 16 + (lane >> 4) * 8) * 2);
                ldsm_x4_trans(vhB + addr, vh[db][0], vh[db][1], vh[db][2], vh[db][3]);
                ldsm_x4_trans(vlB + addr, vl[db][0], vl[db][1], vl[db][2], vl[db][3]);
            }
#pragma unroll
            for (int db = 0; db < 4; db++) {
                mma16816(O[2*db],   pah[ks][0], pah[ks][1], pah[ks][2], pah[ks][3], vh[db][0], vh[db][1]);
                mma16816(O[2*db],   pal[ks][0], pal[ks][1], pal[ks][2], pal[ks][3], vh[db][0], vh[db][1]);
                mma16816(O[2*db],   pah[ks][0], pah[ks][1], pah[ks][2], pah[ks][3], vl[db][0], vl[db][1]);
                mma16816(O[2*db+1], pah[ks][0], pah[ks][1], pah[ks][2], pah[ks][3], vh[db][2], vh[db][3]);
                mma16816(O[2*db+1], pal[ks][0], pal[ks][1], pal[ks][2], pal[ks][3], vh[db][2], vh[db][3]);
                mma16816(O[2*db+1], pah[ks][0], pah[ks][1], pah[ks][2], pah[ks][3], vl[db][2], vl[db][3]);
            }
        }
        __syncthreads();
    }

    // ---- epilogue: O/gamma -> bf16 hi/lo ----
    const float ig = 1.0f / gamma[0];
#pragma unroll
    for (int nt = 0; nt < 8; nt++) {
        int r = row0 + w * 16 + (lane >> 2);
        int col = h * HD_ + nt * 8 + (lane & 3) * 2;
        uint32_t h0, l0, h1, l1;
        pack2_hilo(O[nt][0] * ig, O[nt][1] * ig, h0, l0);
        pack2_hilo(O[nt][2] * ig, O[nt][3] * ig, h1, l1);
        *(uint32_t*)&Ch[(size_t)r * HID_ + col] = h0;
        *(uint32_t*)&Cl[(size_t)r * HID_ + col] = l0;
        *(uint32_t*)&Ch[(size_t)(r + 8) * HID_ + col] = h1;
        *(uint32_t*)&Cl[(size_t)(r + 8) * HID_ + col] = l1;
    }
}

// ============================================================
// Launch
// ============================================================
extern "C" void kernel_launch(void* const* d_in, const int* in_sizes, int n_in,
                              void* d_out, int out_size)
{
    (void)in_sizes; (void)n_in; (void)out_size;
    const float* X    = (const float*)d_in[0];
    const float* mask = (const float*)d_in[1];
    const float* Wq   = (const float*)d_in[2];
    const float* bq   = (const float*)d_in[3];
    const float* Wk   = (const float*)d_in[4];
    const float* bk   = (const float*)d_in[5];
    const float* Wv   = (const float*)d_in[6];
    const float* bv   = (const float*)d_in[7];
    const float* Wo   = (const float*)d_in[8];
    const float* bo   = (const float*)d_in[9];
    const float* gamma = (const float*)d_in[11];   // beta (d_in[10]) cancels exactly
    float* out = (float*)d_out;

    __nv_bfloat16 *xhi, *xlo, *whi, *wlo, *qhp, *qlp, *khp, *klp, *vhp, *vlp, *chp, *clp;
    cudaGetSymbolAddress((void**)&xhi, g_Xhi);
    cudaGetSymbolAddress((void**)&xlo, g_Xlo);
    cudaGetSymbolAddress((void**)&whi, g_Whi);
    cudaGetSymbolAddress((void**)&wlo, g_Wlo);
    cudaGetSymbolAddress((void**)&qhp, g_Qh);
    cudaGetSymbolAddress((void**)&qlp, g_Ql);
    cudaGetSymbolAddress((void**)&khp, g_Kh);
    cudaGetSymbolAddress((void**)&klp, g_Kl);
    cudaGetSymbolAddress((void**)&vhp, g_Vh);
    cudaGetSymbolAddress((void**)&vlp, g_Vl);
    cudaGetSymbolAddress((void**)&chp, g_Ch);
    cudaGetSymbolAddress((void**)&clp, g_Cl);

    const int WN = HID_ * HID_;
    cvt_split<<<(MTOT * HID_ / 4 + 255) / 256, 256>>>(X,  xhi, xlo, MTOT * HID_ / 4);
    cvt_split<<<(WN / 4 + 255) / 256, 256>>>(Wq, whi + 0 * WN, wlo + 0 * WN, WN / 4);
    cvt_split<<<(WN / 4 + 255) / 256, 256>>>(Wk, whi + 1 * WN, wlo + 1 * WN, WN / 4);
    cvt_split<<<(WN / 4 + 255) / 256, 256>>>(Wv, whi + 2 * WN, wlo + 2 * WN, WN / 4);
    cvt_split<<<(WN / 4 + 255) / 256, 256>>>(Wo, whi + 3 * WN, wlo + 3 * WN, WN / 4);

    dim3 gg(HID_ / 128, MTOT / 128);   // (8, 32)
    gemm_mma_bf16x3<true><<<gg, 256>>>(xhi, xlo, whi + 0 * WN, wlo + 0 * WN, bq,
                                       nullptr, qhp, qlp, MTOT, HID_, HID_);
    gemm_mma_bf16x3<true><<<gg, 256>>>(xhi, xlo, whi + 1 * WN, wlo + 1 * WN, bk,
                                       nullptr, khp, klp, MTOT, HID_, HID_);
    gemm_mma_bf16x3<true><<<gg, 256>>>(xhi, xlo, whi + 2 * WN, wlo + 2 * WN, bv,
                                       nullptr, vhp, vlp, MTOT, HID_, HID_);

    dim3 ga(S_ / 64, NH_, B_);         // (32, 16, 2)
    consmax_attn_mma<<<ga, 128>>>(qhp, qlp, khp, klp, vhp, vlp, mask, gamma, chp, clp);

    gemm_mma_bf16x3<false><<<gg, 256>>>(chp, clp, whi + 3 * WN, wlo + 3 * WN, bo,
                                        out, nullptr, nullptr, MTOT, HID_, HID_);
}

// round 5
// speedup vs baseline: 2.6042x; 1.1384x over previous
#include <cuda_runtime.h>
#include <cuda_bf16.h>
#include <math.h>
#include <stdint.h>

#define B_    2
#define S_    2048
#define HID_  1024
#define NH_   16
#define HD_   64
#define MTOT  (B_ * S_)

// ---------------- scratch (static device allocations) ----------------
__device__ __nv_bfloat16 g_Xhi[MTOT * HID_];
__device__ __nv_bfloat16 g_Xlo[MTOT * HID_];
__device__ __nv_bfloat16 g_Whi[4 * HID_ * HID_];
__device__ __nv_bfloat16 g_Wlo[4 * HID_ * HID_];
__device__ __nv_bfloat16 g_Qh[MTOT * HID_];
__device__ __nv_bfloat16 g_Ql[MTOT * HID_];
__device__ __nv_bfloat16 g_Kh[MTOT * HID_];
__device__ __nv_bfloat16 g_Kl[MTOT * HID_];
__device__ __nv_bfloat16 g_Vh[MTOT * HID_];
__device__ __nv_bfloat16 g_Vl[MTOT * HID_];
__device__ __nv_bfloat16 g_Ch[MTOT * HID_];
__device__ __nv_bfloat16 g_Cl[MTOT * HID_];

// ---------------- warp-MMA + cp.async helpers (baseline PTX only) ----------------
__device__ __forceinline__ uint32_t smem_u32(const void* p) {
    uint32_t a;
    asm("{ .reg .u64 t; cvta.to.shared.u64 t, %1; cvt.u32.u64 %0, t; }" : "=r"(a) : "l"(p));
    return a;
}
__device__ __forceinline__ void ldsm_x4(uint32_t addr, uint32_t& r0, uint32_t& r1,
                                        uint32_t& r2, uint32_t& r3) {
    asm volatile("ldmatrix.sync.aligned.m8n8.x4.shared.b16 {%0,%1,%2,%3}, [%4];"
                 : "=r"(r0), "=r"(r1), "=r"(r2), "=r"(r3) : "r"(addr));
}
__device__ __forceinline__ void ldsm_x4_trans(uint32_t addr, uint32_t& r0, uint32_t& r1,
                                              uint32_t& r2, uint32_t& r3) {
    asm volatile("ldmatrix.sync.aligned.m8n8.x4.trans.shared.b16 {%0,%1,%2,%3}, [%4];"
                 : "=r"(r0), "=r"(r1), "=r"(r2), "=r"(r3) : "r"(addr));
}
__device__ __forceinline__ void mma16816(float* c, uint32_t a0, uint32_t a1,
                                         uint32_t a2, uint32_t a3,
                                         uint32_t b0, uint32_t b1) {
    asm volatile(
        "mma.sync.aligned.m16n8k16.row.col.f32.bf16.bf16.f32 "
        "{%0,%1,%2,%3}, {%4,%5,%6,%7}, {%8,%9}, {%0,%1,%2,%3};"
        : "+f"(c[0]), "+f"(c[1]), "+f"(c[2]), "+f"(c[3])
        : "r"(a0), "r"(a1), "r"(a2), "r"(a3), "r"(b0), "r"(b1));
}
__device__ __forceinline__ void pack2_hilo(float a, float b, uint32_t& hi, uint32_t& lo) {
    __nv_bfloat16 ah = __float2bfloat16(a), bh = __float2bfloat16(b);
    float ar = a - __bfloat162float(ah), br = b - __bfloat162float(bh);
    __nv_bfloat16 al = __float2bfloat16(ar), bl = __float2bfloat16(br);
    hi = (uint32_t)(*(unsigned short*)&ah) | ((uint32_t)(*(unsigned short*)&bh) << 16);
    lo = (uint32_t)(*(unsigned short*)&al) | ((uint32_t)(*(unsigned short*)&bl) << 16);
}
#define CP16(dst, src) \
    asm volatile("cp.async.cg.shared.global [%0], [%1], 16;" :: "r"(dst), "l"(src))
#define CP_COMMIT() asm volatile("cp.async.commit_group;")
#define CP_WAIT1()  asm volatile("cp.async.wait_group 1;")

// ---------------- fp32 -> bf16 hi/lo split ----------------
__global__ __launch_bounds__(256) void cvt_split(
    const float* __restrict__ in, __nv_bfloat16* __restrict__ hi,
    __nv_bfloat16* __restrict__ lo, int n4)
{
    int i = blockIdx.x * blockDim.x + threadIdx.x;
    if (i >= n4) return;
    float4 v = ((const float4*)in)[i];
    float x[4] = {v.x, v.y, v.z, v.w};
    __nv_bfloat16 h[4], l[4];
#pragma unroll
    for (int j = 0; j < 4; j++) {
        h[j] = __float2bfloat16(x[j]);
        l[j] = __float2bfloat16(x[j] - __bfloat162float(h[j]));
    }
    ((ushort4*)hi)[i] = make_ushort4(*(unsigned short*)&h[0], *(unsigned short*)&h[1],
                                     *(unsigned short*)&h[2], *(unsigned short*)&h[3]);
    ((ushort4*)lo)[i] = make_ushort4(*(unsigned short*)&l[0], *(unsigned short*)&l[1],
                                     *(unsigned short*)&l[2], *(unsigned short*)&l[3]);
}

// ============================================================
// Tensor-core GEMM, cp.async double-buffered.
// C[M,N] = (A[M,K] @ W[N,K]^T + bias) * oscale
// bf16 hi/lo 3-MMA. CTA tile 128x128, BK=32, 256 threads.
// ============================================================
#define LDA 40
#define G_AS (128 * LDA)                 // elems per array
#define G_STAGE_B (4 * G_AS * 2)         // bytes per stage (40960)
#define G_SMEM_B (2 * G_STAGE_B)         // 81920

template<bool OUT16>
__global__ __launch_bounds__(256) void gemm_mma_bf16x3(
    const __nv_bfloat16* __restrict__ Ahi, const __nv_bfloat16* __restrict__ Alo,
    const __nv_bfloat16* __restrict__ Bhi, const __nv_bfloat16* __restrict__ Blo,
    const float* __restrict__ bias, float* __restrict__ C,
    __nv_bfloat16* __restrict__ Ch, __nv_bfloat16* __restrict__ Cl,
    int M, int N, int K, float oscale)
{
    extern __shared__ char smem[];
    const uint32_t sb = smem_u32(smem);

    const int t    = threadIdx.x;
    const int lane = t & 31;
    const int wid  = t >> 5;
    const int wm   = (wid & 1) * 64;
    const int wn   = (wid >> 1) * 32;
    const int bm   = blockIdx.y * 128;
    const int bn   = blockIdx.x * 128;

    float acc[4][4][4];
#pragma unroll
    for (int i = 0; i < 4; i++)
#pragma unroll
        for (int j = 0; j < 4; j++)
#pragma unroll
            for (int r = 0; r < 4; r++) acc[i][j][r] = 0.0f;

    const int lr = t >> 2;
    const int lc = (t & 3) * 8;

    const uint32_t aOff = (uint32_t)(((wm + (lane & 15)) * LDA + (lane >> 4) * 8) * 2);
    const uint32_t bOff = (uint32_t)(((wn + (lane >> 4) * 8 + (lane & 7)) * LDA + ((lane >> 3) & 1) * 8) * 2);

    // stage loader: 8 x 16B cp.async per thread
#define G_LOAD(s, k0) do {                                                        \
        uint32_t st = sb + (uint32_t)(s) * G_STAGE_B;                             \
        _Pragma("unroll")                                                         \
        for (int bch = 0; bch < 2; bch++) {                                       \
            int r = lr + bch * 64;                                                \
            size_t ga = (size_t)(bm + r) * K + (k0) + lc;                         \
            size_t gb = (size_t)(bn + r) * K + (k0) + lc;                         \
            uint32_t so = (uint32_t)((r * LDA + lc) * 2);                         \
            CP16(st + 0 * G_AS * 2 + so, Ahi + ga);                               \
            CP16(st + 1 * G_AS * 2 + so, Alo + ga);                               \
            CP16(st + 2 * G_AS * 2 + so, Bhi + gb);                               \
            CP16(st + 3 * G_AS * 2 + so, Blo + gb);                               \
        }                                                                         \
    } while (0)

    const int NK = K / 32;
    G_LOAD(0, 0);
    CP_COMMIT();

    for (int it = 0; it < NK; it++) {
        if (it + 1 < NK) G_LOAD((it + 1) & 1, (it + 1) * 32);
        CP_COMMIT();
        CP_WAIT1();
        __syncthreads();

        const uint32_t st   = sb + (uint32_t)(it & 1) * G_STAGE_B;
        const uint32_t aB   = st;
        const uint32_t alB  = st + 1 * G_AS * 2;
        const uint32_t bB   = st + 2 * G_AS * 2;
        const uint32_t blB  = st + 3 * G_AS * 2;

#pragma unroll
        for (int ks = 0; ks < 2; ks++) {
            const uint32_t kb = ks * 32;
            uint32_t bh[8], bl[8];
#pragma unroll
            for (int pr = 0; pr < 2; pr++) {
                uint32_t ba = bOff + (uint32_t)(pr * 16 * LDA * 2) + kb;
                ldsm_x4(bB + ba,  bh[pr*4+0], bh[pr*4+1], bh[pr*4+2], bh[pr*4+3]);
                ldsm_x4(blB + ba, bl[pr*4+0], bl[pr*4+1], bl[pr*4+2], bl[pr*4+3]);
            }
            uint32_t ah[4][4], al[4][4];
#pragma unroll
            for (int mt = 0; mt < 4; mt++) {
                uint32_t aa = aOff + (uint32_t)(mt * 16 * LDA * 2) + kb;
                ldsm_x4(aB + aa,  ah[mt][0], ah[mt][1], ah[mt][2], ah[mt][3]);
                ldsm_x4(alB + aa, al[mt][0], al[mt][1], al[mt][2], al[mt][3]);
            }
#pragma unroll
            for (int mt = 0; mt < 4; mt++) {
#pragma unroll
                for (int nt = 0; nt < 4; nt++) {
                    const int pr = nt >> 1, hf = (nt & 1) * 2;
                    uint32_t b0h = bh[pr*4 + hf], b1h = bh[pr*4 + hf + 1];
                    uint32_t b0l = bl[pr*4 + hf], b1l = bl[pr*4 + hf + 1];
                    mma16816(acc[mt][nt], ah[mt][0], ah[mt][1], ah[mt][2], ah[mt][3], b0h, b1h);
                    mma16816(acc[mt][nt], al[mt][0], al[mt][1], al[mt][2], al[mt][3], b0h, b1h);
                    mma16816(acc[mt][nt], ah[mt][0], ah[mt][1], ah[mt][2], ah[mt][3], b0l, b1l);
                }
            }
        }
        __syncthreads();
    }

#pragma unroll
    for (int mt = 0; mt < 4; mt++) {
#pragma unroll
        for (int nt = 0; nt < 4; nt++) {
            int row = bm + wm + mt * 16 + (lane >> 2);
            int col = bn + wn + nt * 8 + (lane & 3) * 2;
            float2 bvv = *(const float2*)&bias[col];
            float v0x = (acc[mt][nt][0] + bvv.x) * oscale, v0y = (acc[mt][nt][1] + bvv.y) * oscale;
            float v1x = (acc[mt][nt][2] + bvv.x) * oscale, v1y = (acc[mt][nt][3] + bvv.y) * oscale;
            if (OUT16) {
                uint32_t h0, l0, h1, l1;
                pack2_hilo(v0x, v0y, h0, l0);
                pack2_hilo(v1x, v1y, h1, l1);
                *(uint32_t*)&Ch[(size_t)row * N + col] = h0;
                *(uint32_t*)&Cl[(size_t)row * N + col] = l0;
                *(uint32_t*)&Ch[(size_t)(row + 8) * N + col] = h1;
                *(uint32_t*)&Cl[(size_t)(row + 8) * N + col] = l1;
            } else {
                *(float2*)&C[(size_t)row * N + col] = make_float2(v0x, v0y);
                *(float2*)&C[(size_t)(row + 8) * N + col] = make_float2(v1x, v1y);
            }
        }
    }
}

// ============================================================
// Tensor-core flash ConsMax attention, cp.async double-buffered.
// 64 q-rows/CTA (4 warps), Bc=64. Q pre-scaled by 1/8 upstream.
// ============================================================
#define LDV 72
#define A_AS (64 * LDV)                  // elems per array
#define A_STAGE_B (4 * A_AS * 2)         // bytes per stage (36864)
#define A_MASK_OFF (2 * A_STAGE_B)       // 73728
#define A_SMEM_B (A_MASK_OFF + 2 * 256)  // 74240

__global__ __launch_bounds__(128) void consmax_attn_mma(
    const __nv_bfloat16* __restrict__ Qh, const __nv_bfloat16* __restrict__ Ql,
    const __nv_bfloat16* __restrict__ Kh, const __nv_bfloat16* __restrict__ Kl,
    const __nv_bfloat16* __restrict__ Vh, const __nv_bfloat16* __restrict__ Vl,
    const float* __restrict__ mask, const float* __restrict__ gamma,
    __nv_bfloat16* __restrict__ Ch, __nv_bfloat16* __restrict__ Cl)
{
    extern __shared__ char smem[];
    const uint32_t sb = smem_u32(smem);

    const int qb = blockIdx.x, h = blockIdx.y, b = blockIdx.z;
    const int t = threadIdx.x, lane = t & 31, w = t >> 5;
    const int row0 = b * S_ + qb * 64;

    // ---- stage Q tile through stage-0 Kh/Kl areas, ldmatrix into registers ----
    {
        int r = t >> 1, half = t & 1;
        const size_t g = (size_t)(row0 + r) * HID_ + h * HD_ + half * 32;
        char* d0 = smem + (r * LDV + half * 32) * 2;
#pragma unroll
        for (int i = 0; i < 4; i++) {
            *(uint4*)(d0 + i * 16)              = *(const uint4*)(Qh + g + i * 8);
            *(uint4*)(d0 + A_AS * 2 + i * 16)   = *(const uint4*)(Ql + g + i * 8);
        }
    }
    __syncthreads();
    uint32_t qh[4][4], ql[4][4];
#pragma unroll
    for (int ks = 0; ks < 4; ks++) {
        uint32_t addr = (uint32_t)(((w * 16 + (lane & 15)) * LDV + ks * 16 + (lane >> 4) * 8) * 2);
        ldsm_x4(sb + addr,            qh[ks][0], qh[ks][1], qh[ks][2], qh[ks][3]);
        ldsm_x4(sb + A_AS * 2 + addr, ql[ks][0], ql[ks][1], ql[ks][2], ql[ks][3]);
    }
    __syncthreads();

    float m0 = -1e30f, m1 = -1e30f;
    float O[8][4];
#pragma unroll
    for (int nt = 0; nt < 8; nt++)
#pragma unroll
        for (int r = 0; r < 4; r++) O[nt][r] = 0.0f;

#define A_LOAD(s, j0) do {                                                        \
        uint32_t st = sb + (uint32_t)(s) * A_STAGE_B;                             \
        int r = t >> 1, half = t & 1;                                             \
        const size_t g = (size_t)(b * S_ + (j0) + r) * HID_ + h * HD_ + half * 32;\
        uint32_t so = (uint32_t)((r * LDV + half * 32) * 2);                      \
        _Pragma("unroll")                                                         \
        for (int i2 = 0; i2 < 4; i2++) {                                          \
            CP16(st + 0 * A_AS * 2 + so + i2 * 16, Kh + g + i2 * 8);              \
            CP16(st + 1 * A_AS * 2 + so + i2 * 16, Kl + g + i2 * 8);              \
            CP16(st + 2 * A_AS * 2 + so + i2 * 16, Vh + g + i2 * 8);              \
            CP16(st + 3 * A_AS * 2 + so + i2 * 16, Vl + g + i2 * 8);              \
        }                                                                         \
        if (t < 16)                                                               \
            CP16(sb + A_MASK_OFF + (uint32_t)(s) * 256 + t * 16,                  \
                 mask + (size_t)b * S_ + (j0) + t * 4);                           \
    } while (0)

    const int NCH = S_ / 64;
    A_LOAD(0, 0);
    CP_COMMIT();

    for (int it = 0; it < NCH; it++) {
        if (it + 1 < NCH) A_LOAD((it + 1) & 1, (it + 1) * 64);
        CP_COMMIT();
        CP_WAIT1();
        __syncthreads();

        const uint32_t st  = sb + (uint32_t)(it & 1) * A_STAGE_B;
        const uint32_t khB = st;
        const uint32_t klB = st + 1 * A_AS * 2;
        const uint32_t vhB = st + 2 * A_AS * 2;
        const uint32_t vlB = st + 3 * A_AS * 2;
        const float* smask = (const float*)(smem + A_MASK_OFF + (it & 1) * 256);

        // ---- S = Q K^T (3-MMA hi/lo); Q pre-scaled by 1/8 ----
        float sc[8][4];
#pragma unroll
        for (int nt = 0; nt < 8; nt++)
#pragma unroll
            for (int r = 0; r < 4; r++) sc[nt][r] = 0.0f;

#pragma unroll
        for (int ks = 0; ks < 4; ks++) {
            uint32_t bh[4][4], bl[4][4];
#pragma unroll
            for (int nb = 0; nb < 4; nb++) {
                uint32_t addr = (uint32_t)(((nb * 16 + (lane >> 4) * 8 + (lane & 7)) * LDV
                                            + ks * 16 + ((lane >> 3) & 1) * 8) * 2);
                ldsm_x4(khB + addr, bh[nb][0], bh[nb][1], bh[nb][2], bh[nb][3]);
                ldsm_x4(klB + addr, bl[nb][0], bl[nb][1], bl[nb][2], bl[nb][3]);
            }
#pragma unroll
            for (int nb = 0; nb < 4; nb++) {
                mma16816(sc[2*nb],   qh[ks][0], qh[ks][1], qh[ks][2], qh[ks][3], bh[nb][0], bh[nb][1]);
                mma16816(sc[2*nb],   ql[ks][0], ql[ks][1], ql[ks][2], ql[ks][3], bh[nb][0], bh[nb][1]);
                mma16816(sc[2*nb],   qh[ks][0], qh[ks][1], qh[ks][2], qh[ks][3], bl[nb][0], bl[nb][1]);
                mma16816(sc[2*nb+1], qh[ks][0], qh[ks][1], qh[ks][2], qh[ks][3], bh[nb][2], bh[nb][3]);
                mma16816(sc[2*nb+1], ql[ks][0], ql[ks][1], ql[ks][2], ql[ks][3], bh[nb][2], bh[nb][3]);
                mma16816(sc[2*nb+1], qh[ks][0], qh[ks][1], qh[ks][2], qh[ks][3], bl[nb][2], bl[nb][3]);
            }
        }

        // ---- mask + running rowmax ----
        float mn0 = m0, mn1 = m1;
#pragma unroll
        for (int nt = 0; nt < 8; nt++) {
            int col = nt * 8 + (lane & 3) * 2;
            float ma = smask[col], mb2 = smask[col + 1];
            sc[nt][0] += ma; sc[nt][1] += mb2;
            sc[nt][2] += ma; sc[nt][3] += mb2;
            mn0 = fmaxf(mn0, fmaxf(sc[nt][0], sc[nt][1]));
            mn1 = fmaxf(mn1, fmaxf(sc[nt][2], sc[nt][3]));
        }
        mn0 = fmaxf(mn0, __shfl_xor_sync(0xffffffffu, mn0, 1));
        mn0 = fmaxf(mn0, __shfl_xor_sync(0xffffffffu, mn0, 2));
        mn1 = fmaxf(mn1, __shfl_xor_sync(0xffffffffu, mn1, 1));
        mn1 = fmaxf(mn1, __shfl_xor_sync(0xffffffffu, mn1, 2));
        float f0 = __expf(m0 - mn0), f1 = __expf(m1 - mn1);
        m0 = mn0; m1 = mn1;

        // ---- P = exp(s - m), hi/lo split -> A-frags ----
        uint32_t pah[4][4], pal[4][4];
#pragma unroll
        for (int ks = 0; ks < 4; ks++) {
            float p00 = __expf(sc[2*ks][0] - m0),   p01 = __expf(sc[2*ks][1] - m0);
            float p02 = __expf(sc[2*ks][2] - m1),   p03 = __expf(sc[2*ks][3] - m1);
            float p10 = __expf(sc[2*ks+1][0] - m0), p11 = __expf(sc[2*ks+1][1] - m0);
            float p12 = __expf(sc[2*ks+1][2] - m1), p13 = __expf(sc[2*ks+1][3] - m1);
            pack2_hilo(p00, p01, pah[ks][0], pal[ks][0]);
            pack2_hilo(p02, p03, pah[ks][1], pal[ks][1]);
            pack2_hilo(p10, p11, pah[ks][2], pal[ks][2]);
            pack2_hilo(p12, p13, pah[ks][3], pal[ks][3]);
        }

        // ---- rescale O ----
#pragma unroll
        for (int nt = 0; nt < 8; nt++) {
            O[nt][0] *= f0; O[nt][1] *= f0; O[nt][2] *= f1; O[nt][3] *= f1;
        }

        // ---- O += P V (3-MMA hi/lo) ----
#pragma unroll
        for (int ks = 0; ks < 4; ks++) {
            uint32_t vh[4][4], vl[4][4];
#pragma unroll
            for (int db = 0; db < 4; db++) {
                uint32_t addr = (uint32_t)(((ks * 16 + ((lane >> 3) & 1) * 8 + (lane & 7)) * LDV
                                            + db * 16 + (lane >> 4) * 8) * 2);
                ldsm_x4_trans(vhB + addr, vh[db][0], vh[db][1], vh[db][2], vh[db][3]);
                ldsm_x4_trans(vlB + addr, vl[db][0], vl[db][1], vl[db][2], vl[db][3]);
            }
#pragma unroll
            for (int db = 0; db < 4; db++) {
                mma16816(O[2*db],   pah[ks][0], pah[ks][1], pah[ks][2], pah[ks][3], vh[db][0], vh[db][1]);
                mma16816(O[2*db],   pal[ks][0], pal[ks][1], pal[ks][2], pal[ks][3], vh[db][0], vh[db][1]);
                mma16816(O[2*db],   pah[ks][0], pah[ks][1], pah[ks][2], pah[ks][3], vl[db][0], vl[db][1]);
                mma16816(O[2*db+1], pah[ks][0], pah[ks][1], pah[ks][2], pah[ks][3], vh[db][2], vh[db][3]);
                mma16816(O[2*db+1], pal[ks][0], pal[ks][1], pal[ks][2], pal[ks][3], vh[db][2], vh[db][3]);
                mma16816(O[2*db+1], pah[ks][0], pah[ks][1], pah[ks][2], pah[ks][3], vl[db][2], vl[db][3]);
            }
        }
        __syncthreads();
    }

    // ---- epilogue ----
    const float ig = 1.0f / gamma[0];
#pragma unroll
    for (int nt = 0; nt < 8; nt++) {
        int r = row0 + w * 16 + (lane >> 2);
        int col = h * HD_ + nt * 8 + (lane & 3) * 2;
        uint32_t h0, l0, h1, l1;
        pack2_hilo(O[nt][0] * ig, O[nt][1] * ig, h0, l0);
        pack2_hilo(O[nt][2] * ig, O[nt][3] * ig, h1, l1);
        *(uint32_t*)&Ch[(size_t)r * HID_ + col] = h0;
        *(uint32_t*)&Cl[(size_t)r * HID_ + col] = l0;
        *(uint32_t*)&Ch[(size_t)(r + 8) * HID_ + col] = h1;
        *(uint32_t*)&Cl[(size_t)(r + 8) * HID_ + col] = l1;
    }
}

// ============================================================
// Launch
// ============================================================
extern "C" void kernel_launch(void* const* d_in, const int* in_sizes, int n_in,
                              void* d_out, int out_size)
{
    (void)in_sizes; (void)n_in; (void)out_size;
    const float* X    = (const float*)d_in[0];
    const float* mask = (const float*)d_in[1];
    const float* Wq   = (const float*)d_in[2];
    const float* bq   = (const float*)d_in[3];
    const float* Wk   = (const float*)d_in[4];
    const float* bk   = (const float*)d_in[5];
    const float* Wv   = (const float*)d_in[6];
    const float* bv   = (const float*)d_in[7];
    const float* Wo   = (const float*)d_in[8];
    const float* bo   = (const float*)d_in[9];
    const float* gamma = (const float*)d_in[11];   // beta (d_in[10]) cancels exactly
    float* out = (float*)d_out;

    __nv_bfloat16 *xhi, *xlo, *whi, *wlo, *qhp, *qlp, *khp, *klp, *vhp, *vlp, *chp, *clp;
    cudaGetSymbolAddress((void**)&xhi, g_Xhi);
    cudaGetSymbolAddress((void**)&xlo, g_Xlo);
    cudaGetSymbolAddress((void**)&whi, g_Whi);
    cudaGetSymbolAddress((void**)&wlo, g_Wlo);
    cudaGetSymbolAddress((void**)&qhp, g_Qh);
    cudaGetSymbolAddress((void**)&qlp, g_Ql);
    cudaGetSymbolAddress((void**)&khp, g_Kh);
    cudaGetSymbolAddress((void**)&klp, g_Kl);
    cudaGetSymbolAddress((void**)&vhp, g_Vh);
    cudaGetSymbolAddress((void**)&vlp, g_Vl);
    cudaGetSymbolAddress((void**)&chp, g_Ch);
    cudaGetSymbolAddress((void**)&clp, g_Cl);

    cudaFuncSetAttribute(gemm_mma_bf16x3<true>,  cudaFuncAttributeMaxDynamicSharedMemorySize, G_SMEM_B);
    cudaFuncSetAttribute(gemm_mma_bf16x3<false>, cudaFuncAttributeMaxDynamicSharedMemorySize, G_SMEM_B);
    cudaFuncSetAttribute(consmax_attn_mma,       cudaFuncAttributeMaxDynamicSharedMemorySize, A_SMEM_B);

    const int WN = HID_ * HID_;
    cvt_split<<<(MTOT * HID_ / 4 + 255) / 256, 256>>>(X,  xhi, xlo, MTOT * HID_ / 4);
    cvt_split<<<(WN / 4 + 255) / 256, 256>>>(Wq, whi + 0 * WN, wlo + 0 * WN, WN / 4);
    cvt_split<<<(WN / 4 + 255) / 256, 256>>>(Wk, whi + 1 * WN, wlo + 1 * WN, WN / 4);
    cvt_split<<<(WN / 4 + 255) / 256, 256>>>(Wv, whi + 2 * WN, wlo + 2 * WN, WN / 4);
    cvt_split<<<(WN / 4 + 255) / 256, 256>>>(Wo, whi + 3 * WN, wlo + 3 * WN, WN / 4);

    dim3 gg(HID_ / 128, MTOT / 128);   // (8, 32)
    gemm_mma_bf16x3<true><<<gg, 256, G_SMEM_B>>>(xhi, xlo, whi + 0 * WN, wlo + 0 * WN, bq,
                                                 nullptr, qhp, qlp, MTOT, HID_, HID_, 0.125f);
    gemm_mma_bf16x3<true><<<gg, 256, G_SMEM_B>>>(xhi, xlo, whi + 1 * WN, wlo + 1 * WN, bk,
                                                 nullptr, khp, klp, MTOT, HID_, HID_, 1.0f);
    gemm_mma_bf16x3<true><<<gg, 256, G_SMEM_B>>>(xhi, xlo, whi + 2 * WN, wlo + 2 * WN, bv,
                                                 nullptr, vhp, vlp, MTOT, HID_, HID_, 1.0f);

    dim3 ga(S_ / 64, NH_, B_);         // (32, 16, 2)
    consmax_attn_mma<<<ga, 128, A_SMEM_B>>>(qhp, qlp, khp, klp, vhp, vlp, mask, gamma, chp, clp);

    gemm_mma_bf16x3<false><<<gg, 256, G_SMEM_B>>>(chp, clp, whi + 3 * WN, wlo + 3 * WN, bo,
                                                  out, nullptr, nullptr, MTOT, HID_, HID_, 1.0f);
}